// round 3
// baseline (speedup 1.0000x reference)
#include <cuda_runtime.h>
#include <cstdint>

// ---------------------------------------------------------------------------
// Problem constants (fixed shapes from reference setup_inputs)
// ---------------------------------------------------------------------------
#define BB   4
#define TT   4096
#define NN   512
#define DD   1024
#define LL   768
#define HH   8
#define HD   128

// ---------------------------------------------------------------------------
// Scratch (single __device__ array; no allocations anywhere)
// ---------------------------------------------------------------------------
#define OFF_XN  0LL                                  // [B*T, D]      16777216
#define OFF_CN  (OFF_XN + 16777216LL)                // [B*N, L]       1572864
#define OFF_Q   (OFF_CN + 1572864LL)                 // [B*T, D]      16777216
#define OFF_K   (OFF_Q  + 16777216LL)                // [B*N, D]       2097152
#define OFF_V   (OFF_K  + 2097152LL)                 // [B*N, D]       2097152
#define OFF_KM  (OFF_V  + 2097152LL)                 // [B, D]            4096
#define OFF_KS  (OFF_KM + 4096LL)                    // [B, D]            4096
#define OFF_CP  (OFF_KS + 4096LL)                    // [4, B*H,128,128] 2097152
#define OFF_CTX (OFF_CP + 2097152LL)                 // [B*H,128,128]   524288
#define SCRATCH_TOTAL (OFF_CTX + 524288LL)

__device__ float g_buf[SCRATCH_TOTAL];

// ---------------------------------------------------------------------------
// Helpers
// ---------------------------------------------------------------------------
__device__ __forceinline__ float f2tf32(float x) {
    uint32_t u;
    asm("cvt.rna.tf32.f32 %0, %1;" : "=r"(u) : "f"(x));
    return __uint_as_float(u);
}

__device__ __forceinline__ void mma_tf32(float* c, const uint32_t* a, const uint32_t* b) {
    asm volatile(
        "mma.sync.aligned.m16n8k8.row.col.f32.tf32.tf32.f32 "
        "{%0,%1,%2,%3}, {%4,%5,%6,%7}, {%8,%9}, {%0,%1,%2,%3};\n"
        : "+f"(c[0]), "+f"(c[1]), "+f"(c[2]), "+f"(c[3])
        : "r"(a[0]), "r"(a[1]), "r"(a[2]), "r"(a[3]),
          "r"(b[0]), "r"(b[1]));
}

// ---------------------------------------------------------------------------
// LayerNorm: one block per row, values kept in registers (1 read, 1 write)
// ---------------------------------------------------------------------------
template <int DIM>
__global__ void ln_kernel(const float* __restrict__ x, const float* __restrict__ g,
                          const float* __restrict__ bta, float* __restrict__ out) {
    constexpr int PER = DIM / 256;
    const size_t row = blockIdx.x;
    const float* xr = x + row * DIM;
    float v[PER];
    float s = 0.f, sq = 0.f;
#pragma unroll
    for (int i = 0; i < PER; i++) {
        v[i] = xr[threadIdx.x + 256 * i];
        s += v[i];
        sq += v[i] * v[i];
    }
#pragma unroll
    for (int o = 16; o; o >>= 1) {
        s += __shfl_xor_sync(0xffffffffu, s, o);
        sq += __shfl_xor_sync(0xffffffffu, sq, o);
    }
    __shared__ float sm[8], sv[8];
    int w = threadIdx.x >> 5;
    if ((threadIdx.x & 31) == 0) { sm[w] = s; sv[w] = sq; }
    __syncthreads();
    if (threadIdx.x < 32) {
        s = (threadIdx.x < 8) ? sm[threadIdx.x] : 0.f;
        sq = (threadIdx.x < 8) ? sv[threadIdx.x] : 0.f;
#pragma unroll
        for (int o = 4; o; o >>= 1) {
            s += __shfl_xor_sync(0xffffffffu, s, o);
            sq += __shfl_xor_sync(0xffffffffu, sq, o);
        }
        if (threadIdx.x == 0) { sm[0] = s; sv[0] = sq; }
    }
    __syncthreads();
    const float mean = sm[0] * (1.f / DIM);
    const float var = sv[0] * (1.f / DIM) - mean * mean;
    const float rstd = rsqrtf(var + 1e-5f);
    float* orow = out + row * DIM;
#pragma unroll
    for (int i = 0; i < PER; i++) {
        int c = threadIdx.x + 256 * i;
        orow[c] = (v[i] - mean) * rstd * g[c] + bta[c];
    }
}

// ---------------------------------------------------------------------------
// tf32 tensor-core GEMM: C[M,N] = A[M,K] @ W[K,N] (+bias), optionally batched
// 128x128 block tile, BK=16, double-buffered smem, 8 warps (2m x 4n),
// warp tile 64x32 -> 4x4 m16n8k8 mma tiles.
// ---------------------------------------------------------------------------
__global__ void __launch_bounds__(256, 1)
gemm_tf32(const float* __restrict__ A, const float* __restrict__ Bm,
          const float* __restrict__ bias, float* __restrict__ C,
          int M, int Nn, int K, int lda, int ldb, int ldc,
          int Hdiv, long long sA0, long long sA1, long long sB,
          long long sC0, long long sC1) {
    __shared__ float As[2][128][20];   // pad->stride 20: conflict-free frag reads
    __shared__ float Bs[2][16][136];   // pad->stride 136: conflict-free frag reads

    {
        int z = blockIdx.z;
        int zb = z / Hdiv, zh = z % Hdiv;
        A += zb * sA0 + zh * sA1;
        Bm += (long long)z * sB;
        C += zb * sC0 + zh * sC1;
    }

    const int tM = blockIdx.y * 128;
    const int tN = blockIdx.x * 128;
    const int tid = threadIdx.x;
    const int lane = tid & 31, warp = tid >> 5;
    const int m_base = (warp & 1) * 64;
    const int n_base = (warp >> 1) * 32;

    float acc[4][4][4];
#pragma unroll
    for (int i = 0; i < 4; i++)
#pragma unroll
        for (int j = 0; j < 4; j++)
#pragma unroll
            for (int r = 0; r < 4; r++) acc[i][j][r] = 0.f;

    const int arow0 = tid >> 2;          // 0..63 (+64 for second half)
    const int ac = (tid & 3) * 4;        // 0,4,8,12
    const int bkr = tid >> 5;            // 0..7 (+8 for second half)
    const int bc = (tid & 31) * 4;       // 0..124

    const float* Ag = A + (size_t)tM * lda;
    const float* Bg = Bm + tN;
    const int nk = K / 16;

    // prologue: tile 0
#pragma unroll
    for (int j = 0; j < 2; j++) {
        int r = arow0 + j * 64;
        float4 t = *(const float4*)(Ag + (size_t)r * lda + ac);
        As[0][r][ac + 0] = f2tf32(t.x);
        As[0][r][ac + 1] = f2tf32(t.y);
        As[0][r][ac + 2] = f2tf32(t.z);
        As[0][r][ac + 3] = f2tf32(t.w);
    }
#pragma unroll
    for (int j = 0; j < 2; j++) {
        int r = bkr + j * 8;
        float4 t = *(const float4*)(Bg + (size_t)r * ldb + bc);
        Bs[0][r][bc + 0] = f2tf32(t.x);
        Bs[0][r][bc + 1] = f2tf32(t.y);
        Bs[0][r][bc + 2] = f2tf32(t.z);
        Bs[0][r][bc + 3] = f2tf32(t.w);
    }
    __syncthreads();

    int buf = 0;
    for (int kt = 0; kt < nk; kt++) {
        float4 an[2], bn[2];
        const bool has = (kt + 1 < nk);
        if (has) {
            int ko = (kt + 1) * 16;
#pragma unroll
            for (int j = 0; j < 2; j++)
                an[j] = *(const float4*)(Ag + (size_t)(arow0 + j * 64) * lda + ko + ac);
#pragma unroll
            for (int j = 0; j < 2; j++)
                bn[j] = *(const float4*)(Bg + (size_t)(ko + bkr + j * 8) * ldb + bc);
        }

#pragma unroll
        for (int kk = 0; kk < 2; kk++) {
            uint32_t af[4][4];
#pragma unroll
            for (int im = 0; im < 4; im++) {
                int r = m_base + im * 16 + (lane >> 2);
                int c = kk * 8 + (lane & 3);
                af[im][0] = __float_as_uint(As[buf][r][c]);
                af[im][1] = __float_as_uint(As[buf][r + 8][c]);
                af[im][2] = __float_as_uint(As[buf][r][c + 4]);
                af[im][3] = __float_as_uint(As[buf][r + 8][c + 4]);
            }
            uint32_t bf[4][2];
#pragma unroll
            for (int in = 0; in < 4; in++) {
                int cc = n_base + in * 8 + (lane >> 2);
                int kr = kk * 8 + (lane & 3);
                bf[in][0] = __float_as_uint(Bs[buf][kr][cc]);
                bf[in][1] = __float_as_uint(Bs[buf][kr + 4][cc]);
            }
#pragma unroll
            for (int im = 0; im < 4; im++)
#pragma unroll
                for (int in = 0; in < 4; in++)
                    mma_tf32(acc[im][in], af[im], bf[in]);
        }

        if (has) {
            int nb = buf ^ 1;
#pragma unroll
            for (int j = 0; j < 2; j++) {
                int r = arow0 + j * 64;
                As[nb][r][ac + 0] = f2tf32(an[j].x);
                As[nb][r][ac + 1] = f2tf32(an[j].y);
                As[nb][r][ac + 2] = f2tf32(an[j].z);
                As[nb][r][ac + 3] = f2tf32(an[j].w);
            }
#pragma unroll
            for (int j = 0; j < 2; j++) {
                int r = bkr + j * 8;
                Bs[nb][r][bc + 0] = f2tf32(bn[j].x);
                Bs[nb][r][bc + 1] = f2tf32(bn[j].y);
                Bs[nb][r][bc + 2] = f2tf32(bn[j].z);
                Bs[nb][r][bc + 3] = f2tf32(bn[j].w);
            }
        }
        __syncthreads();
        buf ^= 1;
    }

    const bool hb = (bias != nullptr);
#pragma unroll
    for (int im = 0; im < 4; im++) {
        int r0 = tM + m_base + im * 16 + (lane >> 2);
#pragma unroll
        for (int in = 0; in < 4; in++) {
            int c = tN + n_base + in * 8 + 2 * (lane & 3);
            float b0 = 0.f, b1 = 0.f;
            if (hb) { b0 = __ldg(bias + c); b1 = __ldg(bias + c + 1); }
            float2 v0 = make_float2(acc[im][in][0] + b0, acc[im][in][1] + b1);
            float2 v1 = make_float2(acc[im][in][2] + b0, acc[im][in][3] + b1);
            *(float2*)(C + (size_t)r0 * ldc + c) = v0;
            *(float2*)(C + (size_t)(r0 + 8) * ldc + c) = v1;
        }
    }
}

// ---------------------------------------------------------------------------
// q softmax: one warp per 128-wide head row, in-place
// ---------------------------------------------------------------------------
__global__ void softmax_rows128(float* __restrict__ q) {
    const size_t w = (size_t)blockIdx.x * 8 + (threadIdx.x >> 5);
    float4* p = (float4*)(q + w * 128);
    const int lane = threadIdx.x & 31;
    float4 x = p[lane];
    float m = fmaxf(fmaxf(x.x, x.y), fmaxf(x.z, x.w));
#pragma unroll
    for (int o = 16; o; o >>= 1) m = fmaxf(m, __shfl_xor_sync(0xffffffffu, m, o));
    x.x = __expf(x.x - m); x.y = __expf(x.y - m);
    x.z = __expf(x.z - m); x.w = __expf(x.w - m);
    float s = x.x + x.y + x.z + x.w;
#pragma unroll
    for (int o = 16; o; o >>= 1) s += __shfl_xor_sync(0xffffffffu, s, o);
    const float r = 1.f / s;
    x.x *= r; x.y *= r; x.z *= r; x.w *= r;
    p[lane] = x;
}

// ---------------------------------------------------------------------------
// k column softmax stats (max, sumexp over N=512 per (b, d) column)
// grid: (B * D/32) blocks, 128 threads: 32 cols x 4 segments of 128 rows
// ---------------------------------------------------------------------------
__global__ void kcol_stats(const float* __restrict__ k, float* __restrict__ om,
                           float* __restrict__ os) {
    const int b = blockIdx.x >> 5;
    const int cg = blockIdx.x & 31;
    const int cl = threadIdx.x & 31;
    const int seg = threadIdx.x >> 5;
    const int col = cg * 32 + cl;
    const float* p = k + (size_t)b * NN * DD + col;

    float m = -1e30f;
#pragma unroll 4
    for (int i = 0; i < 128; i++) m = fmaxf(m, p[(size_t)(seg * 128 + i) * DD]);

    __shared__ float smx[4][32], ssm[4][32], gmx[32];
    smx[seg][cl] = m;
    __syncthreads();
    if (seg == 0) {
        float M = fmaxf(fmaxf(smx[0][cl], smx[1][cl]), fmaxf(smx[2][cl], smx[3][cl]));
        gmx[cl] = M;
    }
    __syncthreads();
    const float M = gmx[cl];
    float s = 0.f;
#pragma unroll 4
    for (int i = 0; i < 128; i++) s += __expf(p[(size_t)(seg * 128 + i) * DD] - M);
    ssm[seg][cl] = s;
    __syncthreads();
    if (seg == 0) {
        float S = ssm[0][cl] + ssm[1][cl] + ssm[2][cl] + ssm[3][cl];
        om[b * DD + col] = M;
        os[b * DD + col] = S;
    }
}

// ---------------------------------------------------------------------------
// context partials: ctx[b,h,dk,dv] = (1/s_dk) * sum_n exp(k-m_dk) * v
// softmax applied on the fly (softmaxed k never materialized).
// grid: (B*H, 4 splits of N), 256 threads (16x16, each 8x8 outputs)
// ---------------------------------------------------------------------------
__global__ void __launch_bounds__(256)
context_part(const float* __restrict__ k, const float* __restrict__ v,
             const float* __restrict__ km, const float* __restrict__ ks,
             float* __restrict__ cp) {
    const int bh = blockIdx.x;
    const int b = bh >> 3, h = bh & 7;
    const int split = blockIdx.y;
    __shared__ float Ks[32][132], Vs[32][132];

    const float* kb = k + (size_t)b * NN * DD + h * HD;
    const float* vb = v + (size_t)b * NN * DD + h * HD;
    const float* kmb = km + b * DD + h * HD;
    const float* ksb = ks + b * DD + h * HD;

    float acc[8][8];
#pragma unroll
    for (int i = 0; i < 8; i++)
#pragma unroll
        for (int j = 0; j < 8; j++) acc[i][j] = 0.f;

    const int tx = threadIdx.x & 15, ty = threadIdx.x >> 4;

    for (int c = 0; c < 4; c++) {
        const int n0 = split * 128 + c * 32;
        for (int t = threadIdx.x; t < 32 * 128; t += 256) {
            int nn = t >> 7, dd = t & 127;
            Ks[nn][dd] = __expf(kb[(size_t)(n0 + nn) * DD + dd] - kmb[dd]);
            Vs[nn][dd] = vb[(size_t)(n0 + nn) * DD + dd];
        }
        __syncthreads();
#pragma unroll 8
        for (int nn = 0; nn < 32; nn++) {
            float kr[8], vr[8];
#pragma unroll
            for (int i = 0; i < 8; i++) kr[i] = Ks[nn][ty * 8 + i];
#pragma unroll
            for (int j = 0; j < 8; j++) vr[j] = Vs[nn][tx * 8 + j];
#pragma unroll
            for (int i = 0; i < 8; i++)
#pragma unroll
                for (int j = 0; j < 8; j++) acc[i][j] += kr[i] * vr[j];
        }
        __syncthreads();
    }

    float* out = cp + ((size_t)split * 32 + bh) * (HD * HD);
#pragma unroll
    for (int i = 0; i < 8; i++) {
        const int dk = ty * 8 + i;
        const float rs = 1.f / ksb[dk];
#pragma unroll
        for (int j = 0; j < 8; j++)
            out[(size_t)dk * HD + tx * 8 + j] = acc[i][j] * rs;
    }
}

__global__ void ctx_reduce(const float* __restrict__ cp, float* __restrict__ ctx) {
    const size_t i = (size_t)blockIdx.x * 256 + threadIdx.x;
    ctx[i] = cp[i] + cp[i + 524288] + cp[i + 2 * 524288] + cp[i + 3 * 524288];
}

// ---------------------------------------------------------------------------
// Launch
// ---------------------------------------------------------------------------
extern "C" void kernel_launch(void* const* d_in, const int* in_sizes, int n_in,
                              void* d_out, int out_size) {
    const float* x     = (const float*)d_in[0];
    const float* cond  = (const float*)d_in[1];
    const float* ln_g  = (const float*)d_in[2];
    const float* ln_b  = (const float*)d_in[3];
    const float* tln_g = (const float*)d_in[4];
    const float* tln_b = (const float*)d_in[5];
    const float* Wq    = (const float*)d_in[6];
    const float* bq    = (const float*)d_in[7];
    const float* Wk    = (const float*)d_in[8];
    const float* bk    = (const float*)d_in[9];
    const float* Wv    = (const float*)d_in[10];
    const float* bv    = (const float*)d_in[11];
    float* y = (float*)d_out;

    float* base = nullptr;
    cudaGetSymbolAddress((void**)&base, g_buf);
    float* xn  = base + OFF_XN;
    float* cn  = base + OFF_CN;
    float* q   = base + OFF_Q;
    float* kk  = base + OFF_K;
    float* vv  = base + OFF_V;
    float* km  = base + OFF_KM;
    float* ks  = base + OFF_KS;
    float* cp  = base + OFF_CP;
    float* ctx = base + OFF_CTX;

    // 1-2: LayerNorms
    ln_kernel<DD><<<BB * TT, 256>>>(x, ln_g, ln_b, xn);
    ln_kernel<LL><<<BB * NN, 256>>>(cond, tln_g, tln_b, cn);

    // 3: q = xn @ Wq + bq   [16384 x 1024 x 1024]
    gemm_tf32<<<dim3(DD / 128, (BB * TT) / 128, 1), 256>>>(
        xn, Wq, bq, q, BB * TT, DD, DD, DD, DD, DD, 1, 0, 0, 0, 0, 0);

    // 4-5: k,v = cn @ W{k,v} + b   [2048 x 1024 x 768]
    gemm_tf32<<<dim3(DD / 128, (BB * NN) / 128, 1), 256>>>(
        cn, Wk, bk, kk, BB * NN, DD, LL, LL, DD, DD, 1, 0, 0, 0, 0, 0);
    gemm_tf32<<<dim3(DD / 128, (BB * NN) / 128, 1), 256>>>(
        cn, Wv, bv, vv, BB * NN, DD, LL, LL, DD, DD, 1, 0, 0, 0, 0, 0);

    // 6: q softmax over head_dim (in-place)
    softmax_rows128<<<(BB * TT * HH) / 8, 256>>>(q);

    // 7: k column softmax stats (over N)
    kcol_stats<<<BB * (DD / 32), 128>>>(kk, km, ks);

    // 8-9: context = softmax_N(k)^T @ v  (4-way N split + reduce)
    context_part<<<dim3(BB * HH, 4), 256>>>(kk, vv, km, ks, cp);
    ctx_reduce<<<(BB * HH * HD * HD) / 256, 256>>>(cp, ctx);

    // 10: y = q_soft @ ctx, batched over (b,h), writes d_out directly
    gemm_tf32<<<dim3(1, TT / 128, BB * HH), 256>>>(
        q, ctx, nullptr, y, TT, HD, HD, DD, HD, DD,
        HH, (long long)TT * DD, HD, (long long)HD * HD,
        (long long)TT * DD, HD);
}

// round 4
// speedup vs baseline: 1.6066x; 1.6066x over previous
#include <cuda_runtime.h>
#include <cstdint>

// ---------------------------------------------------------------------------
// Problem constants (fixed shapes from reference setup_inputs)
// ---------------------------------------------------------------------------
#define BB   4
#define TT   4096
#define NN   512
#define DD   1024
#define LL   768
#define HH   8
#define HD   128

// ---------------------------------------------------------------------------
// Scratch (single __device__ array; no allocations anywhere)
// ---------------------------------------------------------------------------
#define OFF_XN  0LL                                  // [B*T, D]      16777216
#define OFF_CN  (OFF_XN + 16777216LL)                // [B*N, L]       1572864
#define OFF_Q   (OFF_CN + 1572864LL)                 // [B*T, D]      16777216
#define OFF_K   (OFF_Q  + 16777216LL)                // [B*N, D]       2097152
#define OFF_V   (OFF_K  + 2097152LL)                 // [B*N, D]       2097152
#define OFF_KM  (OFF_V  + 2097152LL)                 // [B, D]            4096
#define OFF_KS  (OFF_KM + 4096LL)                    // [B, D]            4096
#define OFF_CP  (OFF_KS + 4096LL)                    // [4, B*H,128,128] 2097152
#define OFF_CTX (OFF_CP + 2097152LL)                 // [B*H,128,128]   524288
#define SCRATCH_TOTAL (OFF_CTX + 524288LL)

__device__ __align__(256) float g_buf[SCRATCH_TOTAL];

// ---------------------------------------------------------------------------
// Helpers
// ---------------------------------------------------------------------------
__device__ __forceinline__ uint32_t f2tf32u(float x) {
    uint32_t u;
    asm("cvt.rna.tf32.f32 %0, %1;" : "=r"(u) : "f"(x));
    return u;
}

__device__ __forceinline__ void mma_tf32(float* c, const uint32_t* a, const uint32_t* b) {
    asm volatile(
        "mma.sync.aligned.m16n8k8.row.col.f32.tf32.tf32.f32 "
        "{%0,%1,%2,%3}, {%4,%5,%6,%7}, {%8,%9}, {%0,%1,%2,%3};\n"
        : "+f"(c[0]), "+f"(c[1]), "+f"(c[2]), "+f"(c[3])
        : "r"(a[0]), "r"(a[1]), "r"(a[2]), "r"(a[3]),
          "r"(b[0]), "r"(b[1]));
}

__device__ __forceinline__ void cp16(void* s, const void* g) {
    uint32_t sa = (uint32_t)__cvta_generic_to_shared(s);
    asm volatile("cp.async.cg.shared.global [%0], [%1], 16;\n" :: "r"(sa), "l"(g));
}

// ---------------------------------------------------------------------------
// LayerNorm: one block per row, values kept in registers (1 read, 1 write)
// ---------------------------------------------------------------------------
template <int DIM>
__global__ void ln_kernel(const float* __restrict__ x, const float* __restrict__ g,
                          const float* __restrict__ bta, float* __restrict__ out) {
    constexpr int PER = DIM / 256;
    const size_t row = blockIdx.x;
    const float* xr = x + row * DIM;
    float v[PER];
    float s = 0.f, sq = 0.f;
#pragma unroll
    for (int i = 0; i < PER; i++) {
        v[i] = xr[threadIdx.x + 256 * i];
        s += v[i];
        sq += v[i] * v[i];
    }
#pragma unroll
    for (int o = 16; o; o >>= 1) {
        s += __shfl_xor_sync(0xffffffffu, s, o);
        sq += __shfl_xor_sync(0xffffffffu, sq, o);
    }
    __shared__ float sm[8], sv[8];
    int w = threadIdx.x >> 5;
    if ((threadIdx.x & 31) == 0) { sm[w] = s; sv[w] = sq; }
    __syncthreads();
    if (threadIdx.x < 32) {
        s = (threadIdx.x < 8) ? sm[threadIdx.x] : 0.f;
        sq = (threadIdx.x < 8) ? sv[threadIdx.x] : 0.f;
#pragma unroll
        for (int o = 4; o; o >>= 1) {
            s += __shfl_xor_sync(0xffffffffu, s, o);
            sq += __shfl_xor_sync(0xffffffffu, sq, o);
        }
        if (threadIdx.x == 0) { sm[0] = s; sv[0] = sq; }
    }
    __syncthreads();
    const float mean = sm[0] * (1.f / DIM);
    const float var = sv[0] * (1.f / DIM) - mean * mean;
    const float rstd = rsqrtf(var + 1e-5f);
    float* orow = out + row * DIM;
#pragma unroll
    for (int i = 0; i < PER; i++) {
        int c = threadIdx.x + 256 * i;
        orow[c] = (v[i] - mean) * rstd * g[c] + bta[c];
    }
}

// ---------------------------------------------------------------------------
// tf32 tensor-core GEMM: C[M,N] = A[M,K] @ W[K,N] (+bias)
// 128x128 tile, BK=16, cp.async 4-stage pipeline, 2 CTAs/SM target.
// 8 warps (2m x 4n), warp tile 64x32 -> 4x4 m16n8k8.
// FUSE_SM: applies row softmax over the 128-col tile (== one head) in epilogue.
// Dual mode (Bm2 != null): first half of blockIdx.x uses {Bm,bias,C},
// second half {Bm2,bias2,C2} (k & v fused in one launch).
// ---------------------------------------------------------------------------
#define STAGES 4
#define AS_STRIDE 20
#define BS_STRIDE 136
#define A_ST_FLOATS (128 * AS_STRIDE)
#define B_ST_FLOATS (16 * BS_STRIDE)
#define SMEM_FLOATS (STAGES * (A_ST_FLOATS + B_ST_FLOATS))
#define SMEM_BYTES (SMEM_FLOATS * 4)

template <bool FUSE_SM>
__global__ void __launch_bounds__(256, 2)
gemm_tf32(const float* __restrict__ A, const float* __restrict__ Bm,
          const float* __restrict__ bias, float* __restrict__ C,
          const float* __restrict__ Bm2, const float* __restrict__ bias2,
          float* __restrict__ C2,
          int K, int lda, int ldb, int ldc,
          int Hdiv, long long sA0, long long sA1, long long sB,
          long long sC0, long long sC1) {
    extern __shared__ float smem[];
    float* Asm = smem;                         // [STAGES][128][20]
    float* Bsm = smem + STAGES * A_ST_FLOATS;  // [STAGES][16][136]

    int tN;
    if (Bm2 != nullptr) {
        const int half = gridDim.x >> 1;
        if (blockIdx.x >= half) {
            Bm = Bm2; bias = bias2; C = C2;
            tN = (blockIdx.x - half) * 128;
        } else {
            tN = blockIdx.x * 128;
        }
    } else {
        const int z = blockIdx.z;
        const int zb = z / Hdiv, zh = z - zb * Hdiv;
        A += zb * sA0 + zh * sA1;
        Bm += (long long)z * sB;
        C += zb * sC0 + zh * sC1;
        tN = blockIdx.x * 128;
    }
    const int tM = blockIdx.y * 128;
    const int tid = threadIdx.x;
    const int lane = tid & 31, warp = tid >> 5;
    const int m_base = (warp & 1) * 64;
    const int n_base = (warp >> 1) * 32;

    const float* Ag = A + (size_t)tM * lda;
    const float* Bg = Bm + tN;
    const int nk = K >> 4;

    // load indexing (each thread: 2 A chunks + 2 B chunks of 16B per stage)
    const int ar0 = tid >> 2;           // A row (and +64)
    const int ac0 = (tid & 3) * 4;      // A col offset within k-tile
    const int br0 = tid >> 5;           // B k-row (and +8)
    const int bc0 = (tid & 31) * 4;     // B col

    auto issue = [&](int kt) {
        const int st = kt & (STAGES - 1);
        float* Al = Asm + st * A_ST_FLOATS;
        float* Bl = Bsm + st * B_ST_FLOATS;
        const int k0 = kt << 4;
        cp16(Al + ar0 * AS_STRIDE + ac0, Ag + (size_t)ar0 * lda + k0 + ac0);
        cp16(Al + (ar0 + 64) * AS_STRIDE + ac0, Ag + (size_t)(ar0 + 64) * lda + k0 + ac0);
        cp16(Bl + br0 * BS_STRIDE + bc0, Bg + (size_t)(k0 + br0) * ldb + bc0);
        cp16(Bl + (br0 + 8) * BS_STRIDE + bc0, Bg + (size_t)(k0 + br0 + 8) * ldb + bc0);
    };

    float acc[4][4][4];
#pragma unroll
    for (int i = 0; i < 4; i++)
#pragma unroll
        for (int j = 0; j < 4; j++)
#pragma unroll
            for (int r = 0; r < 4; r++) acc[i][j][r] = 0.f;

#pragma unroll
    for (int s = 0; s < STAGES - 1; s++) {
        issue(s);   // nk >= 8 for all launches in this problem
        asm volatile("cp.async.commit_group;\n");
    }

    for (int kt = 0; kt < nk; kt++) {
        if (kt + STAGES - 1 < nk) issue(kt + STAGES - 1);
        asm volatile("cp.async.commit_group;\n");
        asm volatile("cp.async.wait_group %0;\n" :: "n"(STAGES - 1));
        __syncthreads();

        const int st = kt & (STAGES - 1);
        const float* Al = Asm + st * A_ST_FLOATS;
        const float* Bl = Bsm + st * B_ST_FLOATS;
#pragma unroll
        for (int kk = 0; kk < 2; kk++) {
            uint32_t af[4][4];
#pragma unroll
            for (int im = 0; im < 4; im++) {
                const int r = m_base + im * 16 + (lane >> 2);
                const int c = kk * 8 + (lane & 3);
                af[im][0] = f2tf32u(Al[r * AS_STRIDE + c]);
                af[im][1] = f2tf32u(Al[(r + 8) * AS_STRIDE + c]);
                af[im][2] = f2tf32u(Al[r * AS_STRIDE + c + 4]);
                af[im][3] = f2tf32u(Al[(r + 8) * AS_STRIDE + c + 4]);
            }
            uint32_t bf[4][2];
#pragma unroll
            for (int in = 0; in < 4; in++) {
                const int cc = n_base + in * 8 + (lane >> 2);
                const int kr = kk * 8 + (lane & 3);
                bf[in][0] = f2tf32u(Bl[kr * BS_STRIDE + cc]);
                bf[in][1] = f2tf32u(Bl[(kr + 4) * BS_STRIDE + cc]);
            }
#pragma unroll
            for (int im = 0; im < 4; im++)
#pragma unroll
                for (int in = 0; in < 4; in++)
                    mma_tf32(acc[im][in], af[im], bf[in]);
        }
        __syncthreads();
    }

    // -------- epilogue --------
    float b0[4], b1[4];
#pragma unroll
    for (int in = 0; in < 4; in++) {
        if (bias != nullptr) {
            const int c = tN + n_base + in * 8 + 2 * (lane & 3);
            b0[in] = __ldg(bias + c);
            b1[in] = __ldg(bias + c + 1);
        } else { b0[in] = 0.f; b1[in] = 0.f; }
    }
#pragma unroll
    for (int im = 0; im < 4; im++)
#pragma unroll
        for (int in = 0; in < 4; in++) {
            acc[im][in][0] += b0[in];
            acc[im][in][1] += b1[in];
            acc[im][in][2] += b0[in];
            acc[im][in][3] += b1[in];
        }

    if (FUSE_SM) {
        // tile cols (128) == one head: full row softmax here.
        // red[0..511]: per-(row, warp-col-group) max; red[512..1023]: sums.
        float* red = smem;            // safe: loop ended with __syncthreads
        float* red2 = smem + 512;
        const int wn = warp >> 1;

        float m0[4], m1[4];
#pragma unroll
        for (int im = 0; im < 4; im++) {
            float a = -1e30f, b = -1e30f;
#pragma unroll
            for (int in = 0; in < 4; in++) {
                a = fmaxf(a, fmaxf(acc[im][in][0], acc[im][in][1]));
                b = fmaxf(b, fmaxf(acc[im][in][2], acc[im][in][3]));
            }
            a = fmaxf(a, __shfl_xor_sync(0xffffffffu, a, 1));
            a = fmaxf(a, __shfl_xor_sync(0xffffffffu, a, 2));
            b = fmaxf(b, __shfl_xor_sync(0xffffffffu, b, 1));
            b = fmaxf(b, __shfl_xor_sync(0xffffffffu, b, 2));
            m0[im] = a; m1[im] = b;
        }
        if ((lane & 3) == 0) {
#pragma unroll
            for (int im = 0; im < 4; im++) {
                const int r = m_base + im * 16 + (lane >> 2);
                red[r * 4 + wn] = m0[im];
                red[(r + 8) * 4 + wn] = m1[im];
            }
        }
        __syncthreads();
        float M0[4], M1[4];
#pragma unroll
        for (int im = 0; im < 4; im++) {
            const int r = m_base + im * 16 + (lane >> 2);
            M0[im] = fmaxf(fmaxf(red[r * 4], red[r * 4 + 1]),
                           fmaxf(red[r * 4 + 2], red[r * 4 + 3]));
            M1[im] = fmaxf(fmaxf(red[(r + 8) * 4], red[(r + 8) * 4 + 1]),
                           fmaxf(red[(r + 8) * 4 + 2], red[(r + 8) * 4 + 3]));
        }
        float s0[4], s1[4];
#pragma unroll
        for (int im = 0; im < 4; im++) {
            float sa = 0.f, sb = 0.f;
#pragma unroll
            for (int in = 0; in < 4; in++) {
                acc[im][in][0] = __expf(acc[im][in][0] - M0[im]);
                acc[im][in][1] = __expf(acc[im][in][1] - M0[im]);
                acc[im][in][2] = __expf(acc[im][in][2] - M1[im]);
                acc[im][in][3] = __expf(acc[im][in][3] - M1[im]);
                sa += acc[im][in][0] + acc[im][in][1];
                sb += acc[im][in][2] + acc[im][in][3];
            }
            sa += __shfl_xor_sync(0xffffffffu, sa, 1);
            sa += __shfl_xor_sync(0xffffffffu, sa, 2);
            sb += __shfl_xor_sync(0xffffffffu, sb, 1);
            sb += __shfl_xor_sync(0xffffffffu, sb, 2);
            s0[im] = sa; s1[im] = sb;
        }
        if ((lane & 3) == 0) {
#pragma unroll
            for (int im = 0; im < 4; im++) {
                const int r = m_base + im * 16 + (lane >> 2);
                red2[r * 4 + wn] = s0[im];
                red2[(r + 8) * 4 + wn] = s1[im];
            }
        }
        __syncthreads();
#pragma unroll
        for (int im = 0; im < 4; im++) {
            const int r = m_base + im * 16 + (lane >> 2);
            const float inv0 = 1.f / (red2[r * 4] + red2[r * 4 + 1] +
                                      red2[r * 4 + 2] + red2[r * 4 + 3]);
            const float inv1 = 1.f / (red2[(r + 8) * 4] + red2[(r + 8) * 4 + 1] +
                                      red2[(r + 8) * 4 + 2] + red2[(r + 8) * 4 + 3]);
            const int r0 = tM + r;
#pragma unroll
            for (int in = 0; in < 4; in++) {
                const int c = tN + n_base + in * 8 + 2 * (lane & 3);
                *(float2*)(C + (size_t)r0 * ldc + c) =
                    make_float2(acc[im][in][0] * inv0, acc[im][in][1] * inv0);
                *(float2*)(C + (size_t)(r0 + 8) * ldc + c) =
                    make_float2(acc[im][in][2] * inv1, acc[im][in][3] * inv1);
            }
        }
    } else {
#pragma unroll
        for (int im = 0; im < 4; im++) {
            const int r0 = tM + m_base + im * 16 + (lane >> 2);
#pragma unroll
            for (int in = 0; in < 4; in++) {
                const int c = tN + n_base + in * 8 + 2 * (lane & 3);
                *(float2*)(C + (size_t)r0 * ldc + c) =
                    make_float2(acc[im][in][0], acc[im][in][1]);
                *(float2*)(C + (size_t)(r0 + 8) * ldc + c) =
                    make_float2(acc[im][in][2], acc[im][in][3]);
            }
        }
    }
}

// ---------------------------------------------------------------------------
// k column softmax stats (max, sumexp over N=512 per (b, d) column)
// ---------------------------------------------------------------------------
__global__ void kcol_stats(const float* __restrict__ k, float* __restrict__ om,
                           float* __restrict__ os) {
    const int b = blockIdx.x >> 5;
    const int cg = blockIdx.x & 31;
    const int cl = threadIdx.x & 31;
    const int seg = threadIdx.x >> 5;
    const int col = cg * 32 + cl;
    const float* p = k + (size_t)b * NN * DD + col;

    float m = -1e30f;
#pragma unroll 4
    for (int i = 0; i < 128; i++) m = fmaxf(m, p[(size_t)(seg * 128 + i) * DD]);

    __shared__ float smx[4][32], ssm[4][32], gmx[32];
    smx[seg][cl] = m;
    __syncthreads();
    if (seg == 0) {
        float M = fmaxf(fmaxf(smx[0][cl], smx[1][cl]), fmaxf(smx[2][cl], smx[3][cl]));
        gmx[cl] = M;
    }
    __syncthreads();
    const float M = gmx[cl];
    float s = 0.f;
#pragma unroll 4
    for (int i = 0; i < 128; i++) s += __expf(p[(size_t)(seg * 128 + i) * DD] - M);
    ssm[seg][cl] = s;
    __syncthreads();
    if (seg == 0) {
        float S = ssm[0][cl] + ssm[1][cl] + ssm[2][cl] + ssm[3][cl];
        om[b * DD + col] = M;
        os[b * DD + col] = S;
    }
}

// ---------------------------------------------------------------------------
// context partials: ctx[b,h,dk,dv] = (1/s_dk) * sum_n exp(k-m_dk) * v
// ---------------------------------------------------------------------------
__global__ void __launch_bounds__(256)
context_part(const float* __restrict__ k, const float* __restrict__ v,
             const float* __restrict__ km, const float* __restrict__ ks,
             float* __restrict__ cp) {
    const int bh = blockIdx.x;
    const int b = bh >> 3, h = bh & 7;
    const int split = blockIdx.y;
    __shared__ float Ks[32][132], Vs[32][132];

    const float* kb = k + (size_t)b * NN * DD + h * HD;
    const float* vb = v + (size_t)b * NN * DD + h * HD;
    const float* kmb = km + b * DD + h * HD;
    const float* ksb = ks + b * DD + h * HD;

    float acc[8][8];
#pragma unroll
    for (int i = 0; i < 8; i++)
#pragma unroll
        for (int j = 0; j < 8; j++) acc[i][j] = 0.f;

    const int tx = threadIdx.x & 15, ty = threadIdx.x >> 4;

    for (int c = 0; c < 4; c++) {
        const int n0 = split * 128 + c * 32;
        for (int t = threadIdx.x; t < 32 * 128; t += 256) {
            int nn = t >> 7, dd = t & 127;
            Ks[nn][dd] = __expf(kb[(size_t)(n0 + nn) * DD + dd] - kmb[dd]);
            Vs[nn][dd] = vb[(size_t)(n0 + nn) * DD + dd];
        }
        __syncthreads();
#pragma unroll 8
        for (int nn = 0; nn < 32; nn++) {
            float kr[8], vr[8];
#pragma unroll
            for (int i = 0; i < 8; i++) kr[i] = Ks[nn][ty * 8 + i];
#pragma unroll
            for (int j = 0; j < 8; j++) vr[j] = Vs[nn][tx * 8 + j];
#pragma unroll
            for (int i = 0; i < 8; i++)
#pragma unroll
                for (int j = 0; j < 8; j++) acc[i][j] += kr[i] * vr[j];
        }
        __syncthreads();
    }

    float* out = cp + ((size_t)split * 32 + bh) * (HD * HD);
#pragma unroll
    for (int i = 0; i < 8; i++) {
        const int dk = ty * 8 + i;
        const float rs = 1.f / ksb[dk];
#pragma unroll
        for (int j = 0; j < 8; j++)
            out[(size_t)dk * HD + tx * 8 + j] = acc[i][j] * rs;
    }
}

__global__ void ctx_reduce(const float* __restrict__ cp, float* __restrict__ ctx) {
    const size_t i = (size_t)blockIdx.x * 256 + threadIdx.x;
    ctx[i] = cp[i] + cp[i + 524288] + cp[i + 2 * 524288] + cp[i + 3 * 524288];
}

// ---------------------------------------------------------------------------
// Launch
// ---------------------------------------------------------------------------
extern "C" void kernel_launch(void* const* d_in, const int* in_sizes, int n_in,
                              void* d_out, int out_size) {
    const float* x     = (const float*)d_in[0];
    const float* cond  = (const float*)d_in[1];
    const float* ln_g  = (const float*)d_in[2];
    const float* ln_b  = (const float*)d_in[3];
    const float* tln_g = (const float*)d_in[4];
    const float* tln_b = (const float*)d_in[5];
    const float* Wq    = (const float*)d_in[6];
    const float* bq    = (const float*)d_in[7];
    const float* Wk    = (const float*)d_in[8];
    const float* bk    = (const float*)d_in[9];
    const float* Wv    = (const float*)d_in[10];
    const float* bv    = (const float*)d_in[11];
    float* y = (float*)d_out;

    float* base = nullptr;
    cudaGetSymbolAddress((void**)&base, g_buf);
    float* xn  = base + OFF_XN;
    float* cn  = base + OFF_CN;
    float* q   = base + OFF_Q;
    float* kk  = base + OFF_K;
    float* vv  = base + OFF_V;
    float* km  = base + OFF_KM;
    float* ks  = base + OFF_KS;
    float* cp  = base + OFF_CP;
    float* ctx = base + OFF_CTX;

    // allow >48KB dynamic smem (idempotent, not an allocation)
    cudaFuncSetAttribute(gemm_tf32<true>,
                         cudaFuncAttributeMaxDynamicSharedMemorySize, SMEM_BYTES);
    cudaFuncSetAttribute(gemm_tf32<false>,
                         cudaFuncAttributeMaxDynamicSharedMemorySize, SMEM_BYTES);

    // 1-2: LayerNorms
    ln_kernel<DD><<<BB * TT, 256>>>(x, ln_g, ln_b, xn);
    ln_kernel<LL><<<BB * NN, 256>>>(cond, tln_g, tln_b, cn);

    // 3: q = softmax_head(xn @ Wq + bq)   [16384 x 1024 x 1024], fused softmax
    gemm_tf32<true><<<dim3(DD / 128, (BB * TT) / 128, 1), 256, SMEM_BYTES>>>(
        xn, Wq, bq, q, nullptr, nullptr, nullptr,
        DD, DD, DD, DD, 1, 0, 0, 0, 0, 0);

    // 4: k,v = cn @ W{k,v} + b fused in one launch  [2048 x 1024 x 768] x2
    gemm_tf32<false><<<dim3(2 * DD / 128, (BB * NN) / 128, 1), 256, SMEM_BYTES>>>(
        cn, Wk, bk, kk, Wv, bv, vv,
        LL, LL, DD, DD, 1, 0, 0, 0, 0, 0);

    // 5: k column softmax stats (over N)
    kcol_stats<<<BB * (DD / 32), 128>>>(kk, km, ks);

    // 6-7: context = softmax_N(k)^T @ v  (4-way N split + reduce)
    context_part<<<dim3(BB * HH, 4), 256>>>(kk, vv, km, ks, cp);
    ctx_reduce<<<(BB * HH * HD * HD) / 256, 256>>>(cp, ctx);

    // 8: y = q_soft @ ctx, batched over (b,h), writes d_out directly
    gemm_tf32<false><<<dim3(1, TT / 128, BB * HH), 256, SMEM_BYTES>>>(
        q, ctx, nullptr, y, nullptr, nullptr, nullptr,
        HD, DD, HD, DD,
        HH, (long long)TT * DD, HD, (long long)HD * HD,
        (long long)TT * DD, HD);
}